// round 6
// baseline (speedup 1.0000x reference)
#include <cuda_runtime.h>
#include <cstdint>

#define B_  2
#define N_  1024
#define M_  1024
#define H_  128
#define G_  128
#define WBLK_ 8                      // blocks that compute W partial colsums
#define SCALE_ (1.0f / 6.964404506368992f)  // 1 / 128^0.4

__device__ float g_wpart[WBLK_ * H_];   // partial column sums of W
__device__ float g_es[B_ * M_];         // exp(scaled logits)
__device__ float g_psum[G_];            // per-block partial exp sums
__device__ unsigned g_count;            // monotonic ticket barrier (zero-init)

// dynamic smem layout (bytes):
//   [0, 65536)      : float4 buf[4096]  -- output staging (16 rows x 4KB)
//                     aliases: keys tile [0,8192), W staging [8192,16384)
//   [65536, 69632)  : float sh_s[1024]
//   [69632, 70144)  : float sh_wcol[128]
//   [70144, 70208)  : float sh_val[16]
//   [70208, 70272)  : float sh_e[16]
//   [70272, 70288)  : float sh_denom
#define SMEM_BYTES 70400

__device__ __forceinline__ uint32_t smem_u32(const void* p) {
    uint32_t a;
    asm("{ .reg .u64 t; cvta.to.shared.u64 t, %1; cvt.u32.u64 %0, t; }"
        : "=r"(a) : "l"(p));
    return a;
}

__device__ __forceinline__ void gridbar(int tid) {
    __syncthreads();
    if (tid == 0) {
        __threadfence();
        const unsigned ticket = atomicAdd(&g_count, 1u);
        const unsigned target = (ticket / G_ + 1u) * G_;
        while (*((volatile unsigned*)&g_count) < target) { }
        __threadfence();
    }
    __syncthreads();
}

__global__ __launch_bounds__(1024) void k_fused(const float* __restrict__ keys,
                                                const float* __restrict__ values,
                                                const float* __restrict__ W,
                                                float* __restrict__ out) {
    extern __shared__ char smem[];
    float4* buf      = reinterpret_cast<float4*>(smem);
    float4* sh_keys  = buf;                                        // [512] f4
    float4* sh_wtmp  = buf + 512;                                  // [512] f4
    float*  sh_s     = reinterpret_cast<float*>(smem + 65536);
    float*  sh_wcol  = reinterpret_cast<float*>(smem + 69632);
    float*  sh_val   = reinterpret_cast<float*>(smem + 70144);
    float*  sh_e     = reinterpret_cast<float*>(smem + 70208);
    float*  sh_denom = reinterpret_cast<float*>(smem + 70272);

    const int tid  = threadIdx.x;
    const int lane = tid & 31;
    const int warp = tid >> 5;
    const int blk  = blockIdx.x;

    // ---------------- Phase A: prefetch keys/values; W partials (blk<8) -----
    if (warp < 16) {
        sh_keys[warp * 32 + lane] =
            reinterpret_cast<const float4*>(keys)[(blk * 16 + warp) * 32 + lane];
        if (lane == 0) sh_val[warp] = values[blk * 16 + warp];
    } else if (blk < WBLK_) {
        const int r = warp - 16;                     // 0..15
        sh_wtmp[r * 32 + lane] =
            reinterpret_cast<const float4*>(W)[(blk * 16 + r) * 32 + lane];
    }
    __syncthreads();
    if (blk < WBLK_ && tid < 32) {
        float4 s = make_float4(0.f, 0.f, 0.f, 0.f);
        #pragma unroll
        for (int r = 0; r < 16; ++r) {
            float4 p = sh_wtmp[r * 32 + tid];
            s.x += p.x; s.y += p.y; s.z += p.z; s.w += p.w;
        }
        __stcg(reinterpret_cast<float4*>(g_wpart) + blk * 32 + tid, s);
    }

    gridbar(tid);

    // ---------------- Phase B: wcol reduce + 16 row dots + partial expsum ---
    if (tid < H_) {
        float w = 0.f;
        #pragma unroll
        for (int d = 0; d < WBLK_; ++d) w += __ldcg(&g_wpart[d * H_ + tid]);
        sh_wcol[tid] = w;
    }
    __syncthreads();
    if (warp < 16) {
        const float4 k4 = sh_keys[warp * 32 + lane];
        const float4 w4 = reinterpret_cast<const float4*>(sh_wcol)[lane];
        float acc = k4.x * w4.x + k4.y * w4.y + k4.z * w4.z + k4.w * w4.w;
        #pragma unroll
        for (int o = 16; o > 0; o >>= 1) acc += __shfl_xor_sync(0xffffffffu, acc, o);
        if (lane == 0) {
            const float e = __expf(SCALE_ * acc);
            __stcg(&g_es[blk * 16 + warp], e);
            sh_e[warp] = e;
        }
    }
    __syncthreads();
    if (warp == 0) {
        float v = (lane < 16) ? sh_e[lane] : 0.f;
        #pragma unroll
        for (int o = 16; o > 0; o >>= 1) v += __shfl_xor_sync(0xffffffffu, v, o);
        if (lane == 0) __stcg(&g_psum[blk], v);
    }

    gridbar(tid);

    // ---------------- Phase C: denom + softmax row -------------------------
    const int b = blk >> 6;
    const float e = __ldcg(&g_es[b * M_ + tid]);     // issue early
    if (warp == 0) {
        float p = __ldcg(&g_psum[b * 64 + lane]) + __ldcg(&g_psum[b * 64 + 32 + lane]);
        #pragma unroll
        for (int o = 16; o > 0; o >>= 1) p += __shfl_xor_sync(0xffffffffu, p, o);
        if (lane == 0) *sh_denom = p;
    }
    __syncthreads();
    const float inv = 1.0f / *sh_denom;
    sh_s[tid] = e * inv;
    __syncthreads();

    // ---------------- Phase D: stage 16 rows (64 KB), one bulk store -------
    const int r0  = tid >> 8;                        // 0..3
    const int col = tid & 255;
    const float4 s4 = reinterpret_cast<const float4*>(sh_s)[col];
    #pragma unroll
    for (int i = 0; i < 4; ++i) {
        const int rl = i * 4 + r0;                   // local row 0..15
        const float v = sh_val[rl];
        buf[rl * 256 + col] = make_float4(s4.x * v, s4.y * v, s4.z * v, s4.w * v);
    }
    __syncthreads();
    if (tid == 0) {
        asm volatile("fence.proxy.async;" ::: "memory");
        const float* gdst = out + (size_t)blk * 16 * M_;
        asm volatile("cp.async.bulk.global.shared::cta.bulk_group [%0], [%1], %2;"
                     :: "l"(gdst), "r"(smem_u32(buf)), "r"(65536) : "memory");
        asm volatile("cp.async.bulk.commit_group;" ::: "memory");
        asm volatile("cp.async.bulk.wait_group 0;" ::: "memory");
    }
}

extern "C" void kernel_launch(void* const* d_in, const int* in_sizes, int n_in,
                              void* d_out, int out_size) {
    // metadata order: queries, keys, values, W, b  (queries & bias cancel in softmax)
    const float* keys   = (const float*)d_in[1];
    const float* values = (const float*)d_in[2];
    const float* W      = (const float*)d_in[3];
    float* out = (float*)d_out;

    cudaFuncSetAttribute(k_fused, cudaFuncAttributeMaxDynamicSharedMemorySize,
                         SMEM_BYTES);
    k_fused<<<G_, 1024, SMEM_BYTES>>>(keys, values, W, out);
}

// round 8
// speedup vs baseline: 1.1940x; 1.1940x over previous
#include <cuda_runtime.h>
#include <cstdint>

#define B_  2
#define N_  1024
#define M_  1024
#define H_  128
#define SCALE_ (1.0f / 6.964404506368992f)  // 1 / 128^0.4

__device__ float g_wpart[8 * H_];     // partial column sums of W
__device__ float g_es[B_ * M_];       // exp(scaled logits)
__device__ float g_psum[32 * B_];     // per-K1-block partial exp sums (32 per batch)

__device__ __forceinline__ uint32_t smem_u32(const void* p) {
    uint32_t a;
    asm("{ .reg .u64 t; cvta.to.shared.u64 t, %1; cvt.u32.u64 %0, t; }"
        : "=r"(a) : "l"(p));
    return a;
}

// ---------------------------------------------------------------------------
// K0: partial column sums of W. grid 8 x 512; block b handles rows [b*16, b*16+16)
// ---------------------------------------------------------------------------
__global__ __launch_bounds__(512) void k_wpart(const float* __restrict__ W) {
    __shared__ float4 sh[512];
    const int tid = threadIdx.x;
    const int blk = blockIdx.x;
    sh[tid] = reinterpret_cast<const float4*>(W)[(blk * 16 + (tid >> 5)) * 32 + (tid & 31)];
    __syncthreads();
    if (tid < 32) {
        float4 s = make_float4(0.f, 0.f, 0.f, 0.f);
        #pragma unroll
        for (int r = 0; r < 16; ++r) {
            float4 p = sh[r * 32 + tid];
            s.x += p.x; s.y += p.y; s.z += p.z; s.w += p.w;
        }
        __stcg(reinterpret_cast<float4*>(g_wpart) + blk * 32 + tid, s);
    }
}

// ---------------------------------------------------------------------------
// K1: wcol reduce + exp(SCALE * keys.wcol) per row + per-block partial sums.
// grid 64 x 1024; one warp per key row (32 rows per block).
// Batch b's partial sums land in g_psum[b*32 .. b*32+32).
// ---------------------------------------------------------------------------
__global__ __launch_bounds__(1024) void k_exps(const float* __restrict__ keys) {
    __shared__ float sh_wcol[H_];
    __shared__ float sh_e[32];
    const int tid = threadIdx.x;
    const int lane = tid & 31;
    const int warp = tid >> 5;
    const int blk = blockIdx.x;

    if (tid < H_) {
        float w = 0.f;
        #pragma unroll
        for (int d = 0; d < 8; ++d) w += __ldcg(&g_wpart[d * H_ + tid]);
        sh_wcol[tid] = w;
    }
    __syncthreads();

    const int row = blk * 32 + warp;                     // [0, 2048)
    const float4 k4 = reinterpret_cast<const float4*>(keys)[row * 32 + lane];
    const float4 w4 = reinterpret_cast<const float4*>(sh_wcol)[lane];
    float acc = k4.x * w4.x + k4.y * w4.y + k4.z * w4.z + k4.w * w4.w;
    #pragma unroll
    for (int o = 16; o > 0; o >>= 1) acc += __shfl_xor_sync(0xffffffffu, acc, o);
    if (lane == 0) {
        const float e = __expf(SCALE_ * acc);
        __stcg(&g_es[row], e);
        sh_e[warp] = e;
    }
    __syncthreads();
    if (warp == 0) {
        float v = sh_e[lane];
        #pragma unroll
        for (int o = 16; o > 0; o >>= 1) v += __shfl_xor_sync(0xffffffffu, v, o);
        if (lane == 0) __stcg(&g_psum[blk], v);          // blk 0..31 = batch0, 32..63 = batch1
    }
}

// ---------------------------------------------------------------------------
// K2: denom reduce + scale + stage 16 output rows (64 KB) + one bulk store.
// grid 128 x 1024; block b handles output rows [b*16, b*16+16).
// ---------------------------------------------------------------------------
#define K2_SMEM (65536 + 4096 + 64 + 16)
__global__ __launch_bounds__(1024) void k_out(const float* __restrict__ values,
                                              float* __restrict__ out) {
    extern __shared__ char smem[];
    float4* buf    = reinterpret_cast<float4*>(smem);
    float*  sh_s   = reinterpret_cast<float*>(smem + 65536);
    float*  sh_val = reinterpret_cast<float*>(smem + 65536 + 4096);
    float*  sh_inv = reinterpret_cast<float*>(smem + 65536 + 4096 + 64);

    const int tid = threadIdx.x;
    const int lane = tid & 31;
    const int warp = tid >> 5;
    const int blk = blockIdx.x;
    const int b = blk >> 6;                              // 64 blocks per batch

    const float e = __ldcg(&g_es[b * M_ + tid]);
    if (warp == 0) {
        // 32 partials for this batch
        float p = __ldcg(&g_psum[b * 32 + lane]);
        #pragma unroll
        for (int o = 16; o > 0; o >>= 1) p += __shfl_xor_sync(0xffffffffu, p, o);
        if (lane == 0) *sh_inv = 1.0f / p;
    }
    if (warp == 1 && lane < 16) sh_val[lane] = values[blk * 16 + lane];
    __syncthreads();

    sh_s[tid] = e * (*sh_inv);
    __syncthreads();

    const int r0 = tid >> 8;                             // 0..3
    const int col = tid & 255;
    const float4 s4 = reinterpret_cast<const float4*>(sh_s)[col];
    #pragma unroll
    for (int i = 0; i < 4; ++i) {
        const int rl = i * 4 + r0;                       // local row 0..15
        const float v = sh_val[rl];
        buf[rl * 256 + col] = make_float4(s4.x * v, s4.y * v, s4.z * v, s4.w * v);
    }
    __syncthreads();
    if (tid == 0) {
        asm volatile("fence.proxy.async;" ::: "memory");
        const float* gdst = out + (size_t)blk * 16 * M_;
        asm volatile("cp.async.bulk.global.shared::cta.bulk_group [%0], [%1], %2;"
                     :: "l"(gdst), "r"(smem_u32(buf)), "r"(65536) : "memory");
        asm volatile("cp.async.bulk.commit_group;" ::: "memory");
        asm volatile("cp.async.bulk.wait_group 0;" ::: "memory");
    }
}

extern "C" void kernel_launch(void* const* d_in, const int* in_sizes, int n_in,
                              void* d_out, int out_size) {
    // metadata order: queries, keys, values, W, b (queries & bias cancel in softmax)
    const float* keys   = (const float*)d_in[1];
    const float* values = (const float*)d_in[2];
    const float* W      = (const float*)d_in[3];
    float* out = (float*)d_out;

    cudaFuncSetAttribute(k_out, cudaFuncAttributeMaxDynamicSharedMemorySize,
                         K2_SMEM);

    k_wpart<<<8, 512>>>(W);
    k_exps<<<64, 1024>>>(keys);
    k_out<<<128, 1024, K2_SMEM>>>(values, out);
}